// round 4
// baseline (speedup 1.0000x reference)
#include <cuda_runtime.h>
#include <cstdint>

#define H  128
#define NH 8

// Scratch: transposed Wk/Wrk (12 x 128x128) + ping-pong x_m buffers.
__device__ float g_WT[12 * H * H];
__device__ float g_buf0[2304 * H];
__device__ float g_buf1[2304 * H];

__global__ void transpose_k(const float* p0, const float* p1, const float* p2,
                            const float* p3, const float* p4, const float* p5)
{
    const float* ps[6] = {p0, p1, p2, p3, p4, p5};
    int slot = blockIdx.x;                       // 0..11
    const float* Wm = ps[slot >> 1] + (slot & 1) * H * H;
    float* O = g_WT + slot * H * H;
    int t = threadIdx.x;                         // 0..127
    for (int c = 0; c < H; ++c)
        O[c * H + t] = Wm[t * H + c];
}

__device__ __forceinline__ void cp16(uint32_t dst, const float* src) {
    asm volatile("cp.async.cg.shared.global [%0], [%1], 16;" :: "r"(dst), "l"(src));
}

// One block = one query. 128 threads, <=128 regs (4 blocks/SM by regs).
__global__ __launch_bounds__(128, 4) void attn_stage(
    const float* __restrict__ xin, float* __restrict__ xout,
    const float* __restrict__ ksrc, const float* __restrict__ rpesrc,
    const int* __restrict__ knn, const unsigned char* __restrict__ mask,
    const float* __restrict__ Wq,  const float* __restrict__ WkT,
    const float* __restrict__ Wv,  const float* __restrict__ WrkT,
    const float* __restrict__ Wrv, const float* __restrict__ Wo,
    int stage, int S)
{
    extern __shared__ float sm[];
    float* sm_q   = sm;              // 128
    float* sm_qh  = sm + 128;        // 128 (later reused as out_full)
    float* sm_u   = sm + 256;        // 1024  u[i*8+n]
    float* sm_w   = sm + 1280;       // 1024  w[i*8+n]
    float* sm_sc  = sm + 2304;       // 512   half0 partial -> probs [s*8+n]
    float* sm_vb  = sm + 2816;       // 1056  vbar[n*132+i]
    float* sm_rb  = sm + 3872;       // 1056  rbar[n*132+i]
    float* sm_sc1 = sm_vb;           // alias: half1 partial (dead before vb written)
    float* sm_k   = sm + 4928;       // S*132
    float* sm_r   = sm_k + S * 132;  // S*132

    __shared__ int kbase[64];
    __shared__ int rbase[64];
    __shared__ int mflag[64];

    const int q = blockIdx.x;
    const int t = threadIdx.x;

    sm_q[t] = xin[q * H + t];

    if (t < S) {
        int kb, rb, mf;
        if (stage == 1) {
            kb = (q * S + t) * H; rb = kb;
            mf = mask[q * S + t];
        } else if (stage == 2) {
            int idx = knn[q * 32 + t];
            kb = (q * 128 + idx) * H; rb = kb;
            mf = mask[q * 128 + idx];
        } else {
            int g = q / 48, qn = q % 48;
            int idx = knn[(g * 48 + qn) * 16 + t];
            kb = ((g * 48 + idx) * 50 + 49) * H;       // x_a[:, HT-1, :]
            rb = ((g * 48 + qn) * 48 + idx) * H;
            mf = mask[(g * 48 + qn) * 48 + idx];
        }
        kbase[t] = kb; rbase[t] = rb; mflag[t] = mf;
    }
    __syncthreads();

    // Async staging of k / rpe rows (overlaps with qh + u/w compute below).
    {
        uint32_t smk = (uint32_t)__cvta_generic_to_shared(sm_k);
        uint32_t smr = (uint32_t)__cvta_generic_to_shared(sm_r);
        int chunks = S * 32;   // 16B chunks per tensor
        for (int c = t; c < chunks; c += 128) {
            int s = c >> 5, j = c & 31;
            cp16(smk + s * 528 + j * 16, ksrc   + kbase[s] + j * 4);
            cp16(smr + s * 528 + j * 16, rpesrc + rbase[s] + j * 4);
        }
        asm volatile("cp.async.commit_group;");
    }

    // qh = q @ Wq   (4 independent accumulators, bounded unroll)
    {
        float a0 = 0.f, a1 = 0.f, a2 = 0.f, a3 = 0.f;
        #pragma unroll 8
        for (int i = 0; i < H; i += 4) {
            a0 += sm_q[i    ] * Wq[(i    ) * H + t];
            a1 += sm_q[i + 1] * Wq[(i + 1) * H + t];
            a2 += sm_q[i + 2] * Wq[(i + 2) * H + t];
            a3 += sm_q[i + 3] * Wq[(i + 3) * H + t];
        }
        sm_qh[t] = (a0 + a1) + (a2 + a3);
    }
    __syncthreads();

    // u[n][i] = qh_n . WkT rows  (16 acc chains, bounded unroll)
    {
        float uu[NH], ww[NH];
        #pragma unroll
        for (int n = 0; n < NH; ++n) { uu[n] = 0.f; ww[n] = 0.f; }
        #pragma unroll
        for (int n = 0; n < NH; ++n) {
            #pragma unroll 4
            for (int d = 0; d < 16; ++d) {
                float qv = sm_qh[n * 16 + d];
                uu[n] += qv * WkT [(n * 16 + d) * H + t];
                ww[n] += qv * WrkT[(n * 16 + d) * H + t];
            }
        }
        #pragma unroll
        for (int n = 0; n < NH; ++n) { sm_u[t * NH + n] = uu[n]; sm_w[t * NH + n] = ww[n]; }
    }

    asm volatile("cp.async.wait_group 0;");
    __syncthreads();

    // scores: thread = (s, i-half). 8 merged accumulators, float4 smem reads.
    {
        int half = t >> 6, s = t & 63;
        if (s < S) {
            const float* kk = &sm_k[s * 132 + half * 64];
            const float* rr = &sm_r[s * 132 + half * 64];
            const float* ub = sm_u + half * 512;
            const float* wb = sm_w + half * 512;
            float acc[NH];
            #pragma unroll
            for (int n = 0; n < NH; ++n) acc[n] = 0.f;
            #pragma unroll 2
            for (int i = 0; i < 64; i += 4) {
                float4 k4 = *(const float4*)(kk + i);
                float4 r4 = *(const float4*)(rr + i);
                #pragma unroll
                for (int j = 0; j < 4; ++j) {
                    float kv = (j == 0) ? k4.x : (j == 1) ? k4.y : (j == 2) ? k4.z : k4.w;
                    float rv = (j == 0) ? r4.x : (j == 1) ? r4.y : (j == 2) ? r4.z : r4.w;
                    float4 ua = *(const float4*)(ub + (i + j) * 8);
                    float4 u2 = *(const float4*)(ub + (i + j) * 8 + 4);
                    float4 wa = *(const float4*)(wb + (i + j) * 8);
                    float4 w2 = *(const float4*)(wb + (i + j) * 8 + 4);
                    acc[0] += kv * ua.x + rv * wa.x;
                    acc[1] += kv * ua.y + rv * wa.y;
                    acc[2] += kv * ua.z + rv * wa.z;
                    acc[3] += kv * ua.w + rv * wa.w;
                    acc[4] += kv * u2.x + rv * w2.x;
                    acc[5] += kv * u2.y + rv * w2.y;
                    acc[6] += kv * u2.z + rv * w2.z;
                    acc[7] += kv * u2.w + rv * w2.w;
                }
            }
            float* dst = half ? sm_sc1 : sm_sc;
            #pragma unroll
            for (int n = 0; n < NH; ++n) dst[s * NH + n] = acc[n];
        }
    }
    __syncthreads();

    // softmax per head: merge halves, 8 lanes per head, shuffle reduction.
    if (t < 64) {
        int n = t >> 3, j = t & 7;
        float mx = -1e30f;
        for (int s = j; s < S; s += 8) {
            float v = (sm_sc[s * NH + n] + sm_sc1[s * NH + n]) * 0.25f;
            if (mflag[s]) v = -1e9f;
            sm_sc[s * NH + n] = v;
            mx = fmaxf(mx, v);
        }
        #pragma unroll
        for (int o = 4; o; o >>= 1) mx = fmaxf(mx, __shfl_xor_sync(0xffffffffu, mx, o));
        float sum = 0.f;
        for (int s = j; s < S; s += 8) {
            float p = __expf(sm_sc[s * NH + n] - mx);
            sm_sc[s * NH + n] = p; sum += p;
        }
        #pragma unroll
        for (int o = 4; o; o >>= 1) sum += __shfl_xor_sync(0xffffffffu, sum, o);
        float inv = 1.f / sum;
        for (int s = j; s < S; s += 8) sm_sc[s * NH + n] *= inv;
    }
    __syncthreads();

    // vbar[n][i] = sum_s p[n,s] k[s,i];  rbar likewise.
    {
        float vb[NH], rb2[NH];
        #pragma unroll
        for (int n = 0; n < NH; ++n) { vb[n] = 0.f; rb2[n] = 0.f; }
        for (int s = 0; s < S; ++s) {
            float kv = sm_k[s * 132 + t];
            float rv = sm_r[s * 132 + t];
            float4 p0 = *(const float4*)&sm_sc[s * NH];
            float4 p1 = *(const float4*)&sm_sc[s * NH + 4];
            vb[0] += p0.x * kv;  rb2[0] += p0.x * rv;
            vb[1] += p0.y * kv;  rb2[1] += p0.y * rv;
            vb[2] += p0.z * kv;  rb2[2] += p0.z * rv;
            vb[3] += p0.w * kv;  rb2[3] += p0.w * rv;
            vb[4] += p1.x * kv;  rb2[4] += p1.x * rv;
            vb[5] += p1.y * kv;  rb2[5] += p1.y * rv;
            vb[6] += p1.z * kv;  rb2[6] += p1.z * rv;
            vb[7] += p1.w * kv;  rb2[7] += p1.w * rv;
        }
        #pragma unroll
        for (int n = 0; n < NH; ++n) { sm_vb[n * 132 + t] = vb[n]; sm_rb[n * 132 + t] = rb2[n]; }
    }
    __syncthreads();

    // out_full[c] = vbar[n_c] @ Wv[:,c] + rbar[n_c] @ Wrv[:,c]
    {
        int n = t >> 4;
        float o0 = 0.f, o1 = 0.f, o2 = 0.f, o3 = 0.f;
        #pragma unroll 4
        for (int i = 0; i < H; i += 2) {
            o0 += sm_vb[n * 132 + i    ] * Wv [(i    ) * H + t];
            o1 += sm_rb[n * 132 + i    ] * Wrv[(i    ) * H + t];
            o2 += sm_vb[n * 132 + i + 1] * Wv [(i + 1) * H + t];
            o3 += sm_rb[n * 132 + i + 1] * Wrv[(i + 1) * H + t];
        }
        float o = (o0 + o1) + (o2 + o3);
        __syncthreads();
        sm_qh[t] = o;           // reuse as out_full
    }
    __syncthreads();

    // x_new = q + out_full @ Wo
    {
        float x0 = sm_q[t], x1 = 0.f, x2 = 0.f, x3 = 0.f;
        #pragma unroll 8
        for (int c = 0; c < H; c += 4) {
            x0 += sm_qh[c    ] * Wo[(c    ) * H + t];
            x1 += sm_qh[c + 1] * Wo[(c + 1) * H + t];
            x2 += sm_qh[c + 2] * Wo[(c + 2) * H + t];
            x3 += sm_qh[c + 3] * Wo[(c + 3) * H + t];
        }
        xout[q * H + t] = (x0 + x1) + (x2 + x3);
    }
}

extern "C" void kernel_launch(void* const* d_in, const int* in_sizes, int n_in,
                              void* d_out, int out_size)
{
    bool sig = (in_sizes[6] == 32768);

    const float* x_m    = (const float*)d_in[0];
    const float* x_a    = (const float*)d_in[1];
    const float* x_pl   = (const float*)d_in[2];
    const float* rpe_t  = (const float*)d_in[3];
    const float* rpe_pl = (const float*)d_in[4];
    const float* rpe_a  = (const float*)d_in[5];

    const float* W[3][6];
    int wb = sig ? 6 : 11;
    for (int s = 0; s < 3; ++s)
        for (int j = 0; j < 6; ++j)
            W[s][j] = (const float*)d_in[wb + s * 6 + j];

    int kb = sig ? 24 : 6;
    const int* knn_pl = (const int*)d_in[kb + 0];
    const int* knn_a  = (const int*)d_in[kb + 1];
    const unsigned char* mk_t  = (const unsigned char*)d_in[kb + 2];
    const unsigned char* mk_pl = (const unsigned char*)d_in[kb + 3];
    const unsigned char* mk_a  = (const unsigned char*)d_in[kb + 4];

    cudaFuncSetAttribute(attn_stage, cudaFuncAttributeMaxDynamicSharedMemorySize, 73728);
    cudaFuncSetAttribute(attn_stage, cudaFuncAttributePreferredSharedMemoryCarveout, 100);

    float *buf0, *buf1, *wt;
    cudaGetSymbolAddress((void**)&buf0, g_buf0);
    cudaGetSymbolAddress((void**)&buf1, g_buf1);
    cudaGetSymbolAddress((void**)&wt,   g_WT);

    transpose_k<<<12, 128>>>(W[0][1], W[0][3], W[1][1], W[1][3], W[2][1], W[2][3]);

    const int Ss[3] = {50, 32, 16};
    const float* cur = x_m;
    float* bufs[2] = {buf0, buf1};
    int bi = 0;

    for (int l = 0; l < 2; ++l) {
        for (int s = 0; s < 3; ++s) {
            float* outp = (l == 1 && s == 2) ? (float*)d_out : bufs[bi];
            int S = Ss[s];
            const float* ksrc = (s == 1) ? x_pl : x_a;
            const float* rp   = (s == 0) ? rpe_t : (s == 1) ? rpe_pl : rpe_a;
            const int*   kn   = (s == 1) ? knn_pl : (s == 2) ? knn_a : (const int*)0;
            const unsigned char* mk = (s == 0) ? mk_t : (s == 1) ? mk_pl : mk_a;

            const float* Wq   = W[s][0] + l * H * H;
            const float* Wv   = W[s][2] + l * H * H;
            const float* Wrv  = W[s][4] + l * H * H;
            const float* Wo   = W[s][5] + l * H * H;
            const float* WkT  = wt + ((s * 2 + 0) * 2 + l) * H * H;
            const float* WrkT = wt + ((s * 2 + 1) * 2 + l) * H * H;

            size_t smem = (size_t)(4928 + S * 264) * sizeof(float);
            attn_stage<<<2304, 128, smem>>>(cur, outp, ksrc, rp, kn, mk,
                                            Wq, WkT, Wv, WrkT, Wrv, Wo,
                                            s + 1, S);
            cur = outp;
            bi ^= 1;
        }
    }
}

// round 5
// speedup vs baseline: 1.0563x; 1.0563x over previous
#include <cuda_runtime.h>
#include <cstdint>

#define H  128
#define NH 8
#define NQ 2304

// Scratch: transposed Wk/Wrk, u/w/vbar/rbar intermediates, ping-pong x_m.
__device__ float g_WT[12 * H * H];
__device__ float g_u [NQ * 1024];
__device__ float g_w [NQ * 1024];
__device__ float g_vb[NQ * 1024];
__device__ float g_rb[NQ * 1024];
__device__ float g_buf0[NQ * H];
__device__ float g_buf1[NQ * H];

__global__ void transpose_k(const float* p0, const float* p1, const float* p2,
                            const float* p3, const float* p4, const float* p5)
{
    const float* ps[6] = {p0, p1, p2, p3, p4, p5};
    int slot = blockIdx.x;                       // 0..11
    const float* Wm = ps[slot >> 1] + (slot & 1) * H * H;
    float* O = g_WT + slot * H * H;
    int t = threadIdx.x;
    for (int c = 0; c < H; ++c)
        O[c * H + t] = Wm[t * H + c];
}

__device__ __forceinline__ void cp16(uint32_t dst, const float* src) {
    asm volatile("cp.async.cg.shared.global [%0], [%1], 16;" :: "r"(dst), "l"(src));
}

// ---------------- Kernel A: qh = x@Wq; u/w = per-head qh @ WkT/WrkT ----------
// block = 16 queries, 128 threads (thread = column).
__global__ __launch_bounds__(128) void stage_uw(
    const float* __restrict__ xin,
    const float* __restrict__ Wq,
    const float* __restrict__ WkT, const float* __restrict__ WrkT,
    float* __restrict__ gu, float* __restrict__ gw)
{
    __shared__ float sx [16][128];
    __shared__ float sqh[16][128];
    const int t  = threadIdx.x;
    const int q0 = blockIdx.x * 16;

    #pragma unroll
    for (int q = 0; q < 16; ++q) sx[q][t] = xin[(q0 + q) * H + t];
    __syncthreads();

    // qh[q][t] = sum_i x[q][i] * Wq[i][t]   (weights reused 16x)
    {
        float acc[16];
        #pragma unroll
        for (int q = 0; q < 16; ++q) acc[q] = 0.f;
        #pragma unroll 4
        for (int i = 0; i < H; ++i) {
            float wv = Wq[i * H + t];
            #pragma unroll
            for (int q = 0; q < 16; ++q) acc[q] += sx[q][i] * wv;
        }
        #pragma unroll
        for (int q = 0; q < 16; ++q) sqh[q][t] = acc[q];
    }
    __syncthreads();

    // u[q][n][t] = sum_d qh[q][n*16+d] * WkT[(n*16+d)][t]; w likewise.
    #pragma unroll 1
    for (int n = 0; n < NH; ++n) {
        float wk[16], wr[16];
        #pragma unroll
        for (int d = 0; d < 16; ++d) {
            wk[d] = WkT [(n * 16 + d) * H + t];
            wr[d] = WrkT[(n * 16 + d) * H + t];
        }
        #pragma unroll 1
        for (int q = 0; q < 16; ++q) {
            const float4* qh4 = (const float4*)&sqh[q][n * 16];
            float u0 = 0.f, u1 = 0.f, w0 = 0.f, w1 = 0.f;
            #pragma unroll
            for (int v = 0; v < 4; ++v) {
                float4 qv = qh4[v];
                u0 += qv.x * wk[v*4+0] + qv.y * wk[v*4+1];
                u1 += qv.z * wk[v*4+2] + qv.w * wk[v*4+3];
                w0 += qv.x * wr[v*4+0] + qv.y * wr[v*4+1];
                w1 += qv.z * wr[v*4+2] + qv.w * wr[v*4+3];
            }
            gu[(q0 + q) * 1024 + n * H + t] = u0 + u1;
            gw[(q0 + q) * 1024 + n * H + t] = w0 + w1;
        }
    }
}

// ---------------- Kernel B: weight-free attention core -----------------------
// block = 1 query, 128 threads.
__global__ __launch_bounds__(128) void attn_core(
    const float* __restrict__ gu, const float* __restrict__ gw,
    const float* __restrict__ ksrc, const float* __restrict__ rpesrc,
    const int* __restrict__ knn, const unsigned char* __restrict__ mask,
    float* __restrict__ gvb, float* __restrict__ grb,
    int stage, int S)
{
    extern __shared__ float sm[];
    float* sm_u   = sm;              // 1024  [n*128+i]
    float* sm_w   = sm + 1024;       // 1024
    float* sm_sc  = sm + 2048;       // 512   half0 partials -> probs [s*8+n]
    float* sm_sc1 = sm + 2560;       // 512   half1 partials
    float* sm_k   = sm + 3072;       // S*132
    float* sm_r   = sm_k + S * 132;  // S*132

    __shared__ int kbase[64], rbase[64], mflag[64];

    const int q = blockIdx.x;
    const int t = threadIdx.x;

    if (t < S) {
        int kb, rb, mf;
        if (stage == 1) {
            kb = (q * S + t) * H; rb = kb;
            mf = mask[q * S + t];
        } else if (stage == 2) {
            int idx = knn[q * 32 + t];
            kb = (q * 128 + idx) * H; rb = kb;
            mf = mask[q * 128 + idx];
        } else {
            int g = q / 48, qn = q % 48;
            int idx = knn[(g * 48 + qn) * 16 + t];
            kb = ((g * 48 + idx) * 50 + 49) * H;       // x_a[:, HT-1, :]
            rb = ((g * 48 + qn) * 48 + idx) * H;
            mf = mask[(g * 48 + qn) * 48 + idx];
        }
        kbase[t] = kb; rbase[t] = rb; mflag[t] = mf;
    }
    __syncthreads();

    {
        uint32_t su  = (uint32_t)__cvta_generic_to_shared(sm_u);
        uint32_t sw  = (uint32_t)__cvta_generic_to_shared(sm_w);
        for (int c = t; c < 256; c += 128) {
            cp16(su + c * 16, gu + q * 1024 + c * 4);
            cp16(sw + c * 16, gw + q * 1024 + c * 4);
        }
        uint32_t smk = (uint32_t)__cvta_generic_to_shared(sm_k);
        uint32_t smr = (uint32_t)__cvta_generic_to_shared(sm_r);
        for (int c = t; c < S * 32; c += 128) {
            int s = c >> 5, j = c & 31;
            cp16(smk + s * 528 + j * 16, ksrc   + kbase[s] + j * 4);
            cp16(smr + s * 528 + j * 16, rpesrc + rbase[s] + j * 4);
        }
        asm volatile("cp.async.commit_group;");
        asm volatile("cp.async.wait_group 0;");
    }
    __syncthreads();

    // scores: thread = (s, i-half), 8 merged accumulators, float4 LDS.
    {
        int half = t >> 6, s = t & 63;
        if (s < S) {
            const float* kk = &sm_k[s * 132 + half * 64];
            const float* rr = &sm_r[s * 132 + half * 64];
            float acc[NH];
            #pragma unroll
            for (int n = 0; n < NH; ++n) acc[n] = 0.f;
            #pragma unroll 4
            for (int i = 0; i < 64; i += 4) {
                float4 k4 = *(const float4*)(kk + i);
                float4 r4 = *(const float4*)(rr + i);
                #pragma unroll
                for (int n = 0; n < NH; ++n) {
                    float4 u4 = *(const float4*)(sm_u + n * H + half * 64 + i);
                    float4 w4 = *(const float4*)(sm_w + n * H + half * 64 + i);
                    acc[n] += k4.x * u4.x + k4.y * u4.y + k4.z * u4.z + k4.w * u4.w
                            + r4.x * w4.x + r4.y * w4.y + r4.z * w4.z + r4.w * w4.w;
                }
            }
            float* dst = half ? sm_sc1 : sm_sc;
            #pragma unroll
            for (int n = 0; n < NH; ++n) dst[s * NH + n] = acc[n];
        }
    }
    __syncthreads();

    // softmax per head (merge halves, mask, 8 lanes per head).
    if (t < 64) {
        int n = t >> 3, j = t & 7;
        float mx = -1e30f;
        for (int s = j; s < S; s += 8) {
            float v = (sm_sc[s * NH + n] + sm_sc1[s * NH + n]) * 0.25f;
            if (mflag[s]) v = -1e9f;
            sm_sc[s * NH + n] = v;
            mx = fmaxf(mx, v);
        }
        #pragma unroll
        for (int o = 4; o; o >>= 1) mx = fmaxf(mx, __shfl_xor_sync(0xffffffffu, mx, o));
        float sum = 0.f;
        for (int s = j; s < S; s += 8) {
            float p = __expf(sm_sc[s * NH + n] - mx);
            sm_sc[s * NH + n] = p; sum += p;
        }
        #pragma unroll
        for (int o = 4; o; o >>= 1) sum += __shfl_xor_sync(0xffffffffu, sum, o);
        float inv = 1.f / sum;
        for (int s = j; s < S; s += 8) sm_sc[s * NH + n] *= inv;
    }
    __syncthreads();

    // vbar[n][t] = sum_s p[n,s] k[s,t]; rbar likewise; write straight to gmem.
    {
        float vb[NH], rb2[NH];
        #pragma unroll
        for (int n = 0; n < NH; ++n) { vb[n] = 0.f; rb2[n] = 0.f; }
        for (int s = 0; s < S; ++s) {
            float kv = sm_k[s * 132 + t];
            float rv = sm_r[s * 132 + t];
            float4 p0 = *(const float4*)&sm_sc[s * NH];
            float4 p1 = *(const float4*)&sm_sc[s * NH + 4];
            vb[0] += p0.x * kv;  rb2[0] += p0.x * rv;
            vb[1] += p0.y * kv;  rb2[1] += p0.y * rv;
            vb[2] += p0.z * kv;  rb2[2] += p0.z * rv;
            vb[3] += p0.w * kv;  rb2[3] += p0.w * rv;
            vb[4] += p1.x * kv;  rb2[4] += p1.x * rv;
            vb[5] += p1.y * kv;  rb2[5] += p1.y * rv;
            vb[6] += p1.z * kv;  rb2[6] += p1.z * rv;
            vb[7] += p1.w * kv;  rb2[7] += p1.w * rv;
        }
        #pragma unroll
        for (int n = 0; n < NH; ++n) {
            gvb[q * 1024 + n * H + t] = vb[n];
            grb[q * 1024 + n * H + t] = rb2[n];
        }
    }
}

// ---------------- Kernel C: of = vb@Wv + rb@Wrv (per head); x += of@Wo -------
// block = 8 queries, 128 threads.
__global__ __launch_bounds__(128) void out_proj(
    const float* __restrict__ xin,
    const float* __restrict__ gvb, const float* __restrict__ grb,
    const float* __restrict__ Wv, const float* __restrict__ Wrv,
    const float* __restrict__ Wo,
    float* __restrict__ xout)
{
    extern __shared__ float smc[];
    float* svb = smc;             // 8*1024
    float* srb = smc + 8192;      // 8*1024
    float* sx  = smc + 16384;     // 8*128
    float* sof = smc + 17408;     // 8*128

    const int t  = threadIdx.x;
    const int q0 = blockIdx.x * 8;

    {
        uint32_t a = (uint32_t)__cvta_generic_to_shared(svb);
        uint32_t b = (uint32_t)__cvta_generic_to_shared(srb);
        for (int c = t; c < 2048; c += 128) {
            cp16(a + c * 16, gvb + q0 * 1024 + c * 4);
            cp16(b + c * 16, grb + q0 * 1024 + c * 4);
        }
        uint32_t xs = (uint32_t)__cvta_generic_to_shared(sx);
        for (int c = t; c < 256; c += 128)
            cp16(xs + c * 16, xin + q0 * H + c * 4);
        asm volatile("cp.async.commit_group;");
        asm volatile("cp.async.wait_group 0;");
    }
    __syncthreads();

    // of[q][t] = vb[q][n_t]·Wv[:,t] + rb[q][n_t]·Wrv[:,t]
    {
        const int n = t >> 4;
        float acc[8];
        #pragma unroll
        for (int q = 0; q < 8; ++q) acc[q] = 0.f;
        #pragma unroll 4
        for (int i = 0; i < H; ++i) {
            float wv = Wv [i * H + t];
            float wr = Wrv[i * H + t];
            #pragma unroll
            for (int q = 0; q < 8; ++q)
                acc[q] += svb[q * 1024 + n * H + i] * wv
                        + srb[q * 1024 + n * H + i] * wr;
        }
        #pragma unroll
        for (int q = 0; q < 8; ++q) sof[q * H + t] = acc[q];
    }
    __syncthreads();

    // x_out = x + of @ Wo
    {
        float o[8];
        #pragma unroll
        for (int q = 0; q < 8; ++q) o[q] = sx[q * H + t];
        #pragma unroll 4
        for (int i = 0; i < H; ++i) {
            float wo = Wo[i * H + t];
            #pragma unroll
            for (int q = 0; q < 8; ++q) o[q] += sof[q * H + i] * wo;
        }
        #pragma unroll
        for (int q = 0; q < 8; ++q) xout[(q0 + q) * H + t] = o[q];
    }
}

extern "C" void kernel_launch(void* const* d_in, const int* in_sizes, int n_in,
                              void* d_out, int out_size)
{
    bool sig = (in_sizes[6] == 32768);

    const float* x_m    = (const float*)d_in[0];
    const float* x_a    = (const float*)d_in[1];
    const float* x_pl   = (const float*)d_in[2];
    const float* rpe_t  = (const float*)d_in[3];
    const float* rpe_pl = (const float*)d_in[4];
    const float* rpe_a  = (const float*)d_in[5];

    const float* W[3][6];
    int wb = sig ? 6 : 11;
    for (int s = 0; s < 3; ++s)
        for (int j = 0; j < 6; ++j)
            W[s][j] = (const float*)d_in[wb + s * 6 + j];

    int kb = sig ? 24 : 6;
    const int* knn_pl = (const int*)d_in[kb + 0];
    const int* knn_a  = (const int*)d_in[kb + 1];
    const unsigned char* mk_t  = (const unsigned char*)d_in[kb + 2];
    const unsigned char* mk_pl = (const unsigned char*)d_in[kb + 3];
    const unsigned char* mk_a  = (const unsigned char*)d_in[kb + 4];

    cudaFuncSetAttribute(attn_core, cudaFuncAttributeMaxDynamicSharedMemorySize, 65088);
    cudaFuncSetAttribute(out_proj,  cudaFuncAttributeMaxDynamicSharedMemorySize, 73728);

    float *buf0, *buf1, *wt, *gu, *gw, *gvb, *grb;
    cudaGetSymbolAddress((void**)&buf0, g_buf0);
    cudaGetSymbolAddress((void**)&buf1, g_buf1);
    cudaGetSymbolAddress((void**)&wt,   g_WT);
    cudaGetSymbolAddress((void**)&gu,   g_u);
    cudaGetSymbolAddress((void**)&gw,   g_w);
    cudaGetSymbolAddress((void**)&gvb,  g_vb);
    cudaGetSymbolAddress((void**)&grb,  g_rb);

    transpose_k<<<12, 128>>>(W[0][1], W[0][3], W[1][1], W[1][3], W[2][1], W[2][3]);

    const int Ss[3] = {50, 32, 16};
    const float* cur = x_m;
    float* bufs[2] = {buf0, buf1};
    int bi = 0;

    for (int l = 0; l < 2; ++l) {
        for (int s = 0; s < 3; ++s) {
            float* outp = (l == 1 && s == 2) ? (float*)d_out : bufs[bi];
            int S = Ss[s];
            const float* ksrc = (s == 1) ? x_pl : x_a;
            const float* rp   = (s == 0) ? rpe_t : (s == 1) ? rpe_pl : rpe_a;
            const int*   kn   = (s == 1) ? knn_pl : (s == 2) ? knn_a : (const int*)0;
            const unsigned char* mk = (s == 0) ? mk_t : (s == 1) ? mk_pl : mk_a;

            const float* Wq   = W[s][0] + l * H * H;
            const float* Wv   = W[s][2] + l * H * H;
            const float* Wrv  = W[s][4] + l * H * H;
            const float* Wo   = W[s][5] + l * H * H;
            const float* WkT  = wt + ((s * 2 + 0) * 2 + l) * H * H;
            const float* WrkT = wt + ((s * 2 + 1) * 2 + l) * H * H;

            stage_uw<<<NQ / 16, 128>>>(cur, Wq, WkT, WrkT, gu, gw);

            size_t smemB = (size_t)(3072 + S * 264) * sizeof(float);
            attn_core<<<NQ, 128, smemB>>>(gu, gw, ksrc, rp, kn, mk,
                                          gvb, grb, s + 1, S);

            out_proj<<<NQ / 8, 128, 73728>>>(cur, gvb, grb, Wv, Wrv, Wo, outp);

            cur = outp;
            bi ^= 1;
        }
    }
}

// round 6
// speedup vs baseline: 1.1874x; 1.1241x over previous
#include <cuda_runtime.h>
#include <cstdint>

#define H  128
#define NH 8
#define NQ 2304

__device__ float g_WT[12 * H * H];
__device__ float g_u [NQ * 1024];
__device__ float g_w [NQ * 1024];
__device__ float g_vb[NQ * 1024];
__device__ float g_rb[NQ * 1024];
__device__ float g_buf0[NQ * H];
__device__ float g_buf1[NQ * H];

__global__ void transpose_k(const float* p0, const float* p1, const float* p2,
                            const float* p3, const float* p4, const float* p5)
{
    const float* ps[6] = {p0, p1, p2, p3, p4, p5};
    int slot = blockIdx.x >> 2;                  // 0..11
    int part = blockIdx.x & 3;                   // row quarter
    const float* Wm = ps[slot >> 1] + (slot & 1) * H * H;
    float* O = g_WT + slot * H * H;
    int t = threadIdx.x;
    for (int c = part * 32; c < part * 32 + 32; ++c)
        O[c * H + t] = Wm[t * H + c];
}

__device__ __forceinline__ void cp16(uint32_t dst, const float* src) {
    asm volatile("cp.async.cg.shared.global [%0], [%1], 16;" :: "r"(dst), "l"(src));
}

// ---------------- Kernel A: qh = x@Wq; u/w = per-head qh @ WkT/WrkT ----------
// block = 8 queries, 256 threads. g = tid>>7 splits work.
__global__ __launch_bounds__(256) void stage_uw(
    const float* __restrict__ xin,
    const float* __restrict__ Wq,
    const float* __restrict__ WkT, const float* __restrict__ WrkT,
    float* __restrict__ gu, float* __restrict__ gw)
{
    __shared__ float sx [8][128];
    __shared__ float sqh[8][128];
    const int tid = threadIdx.x;
    const int t = tid & 127, g = tid >> 7;
    const int q0 = blockIdx.x * 8;

    for (int e = tid; e < 1024; e += 256)
        sx[e >> 7][e & 127] = xin[q0 * H + e];
    __syncthreads();

    // qh: group g computes queries [4g, 4g+4)
    {
        float a0 = 0.f, a1 = 0.f, a2 = 0.f, a3 = 0.f;
        const float* x0 = sx[4 * g + 0];
        const float* x1 = sx[4 * g + 1];
        const float* x2 = sx[4 * g + 2];
        const float* x3 = sx[4 * g + 3];
        #pragma unroll 8
        for (int i = 0; i < H; ++i) {
            float wv = Wq[i * H + t];
            a0 += x0[i] * wv; a1 += x1[i] * wv;
            a2 += x2[i] * wv; a3 += x3[i] * wv;
        }
        sqh[4 * g + 0][t] = a0; sqh[4 * g + 1][t] = a1;
        sqh[4 * g + 2][t] = a2; sqh[4 * g + 3][t] = a3;
    }
    __syncthreads();

    // u/w: group g handles heads [4g, 4g+4); all 8 queries per head.
    #pragma unroll 1
    for (int nn = 0; nn < 4; ++nn) {
        int n = 4 * g + nn;
        float wk[16], wr[16];
        #pragma unroll
        for (int d = 0; d < 16; ++d) {
            wk[d] = WkT [(n * 16 + d) * H + t];
            wr[d] = WrkT[(n * 16 + d) * H + t];
        }
        float uo[8], wo[8];
        #pragma unroll
        for (int q = 0; q < 8; ++q) { uo[q] = 0.f; wo[q] = 0.f; }
        #pragma unroll
        for (int d = 0; d < 16; ++d) {
            #pragma unroll
            for (int q = 0; q < 8; ++q) {
                float qv = sqh[q][n * 16 + d];
                uo[q] += qv * wk[d];
                wo[q] += qv * wr[d];
            }
        }
        #pragma unroll
        for (int q = 0; q < 8; ++q) {
            gu[(q0 + q) * 1024 + n * H + t] = uo[q];
            gw[(q0 + q) * 1024 + n * H + t] = wo[q];
        }
    }
}

// ---------------- Kernel B: weight-free attention core -----------------------
// block = 1 query, 128 threads.
__global__ __launch_bounds__(128) void attn_core(
    const float* __restrict__ gu, const float* __restrict__ gw,
    const float* __restrict__ ksrc, const float* __restrict__ rpesrc,
    const int* __restrict__ knn, const unsigned char* __restrict__ mask,
    float* __restrict__ gvb, float* __restrict__ grb,
    int stage, int S)
{
    extern __shared__ float sm[];
    float* sm_u   = sm;              // 1024  [n*128+i]
    float* sm_w   = sm + 1024;       // 1024
    float* sm_sc  = sm + 2048;       // 512   half0 partials -> probs [s*8+n]
    float* sm_sc1 = sm + 2560;       // 512   half1 partials
    float* sm_k   = sm + 3072;       // S*132
    float* sm_r   = sm_k + S * 132;  // S*132

    __shared__ int kbase[64], rbase[64], mflag[64];

    const int q = blockIdx.x;
    const int t = threadIdx.x;

    if (t < S) {
        int kb, rb, mf;
        if (stage == 1) {
            kb = (q * S + t) * H; rb = kb;
            mf = mask[q * S + t];
        } else if (stage == 2) {
            int idx = knn[q * 32 + t];
            kb = (q * 128 + idx) * H; rb = kb;
            mf = mask[q * 128 + idx];
        } else {
            int g = q / 48, qn = q % 48;
            int idx = knn[(g * 48 + qn) * 16 + t];
            kb = ((g * 48 + idx) * 50 + 49) * H;       // x_a[:, HT-1, :]
            rb = ((g * 48 + qn) * 48 + idx) * H;
            mf = mask[(g * 48 + qn) * 48 + idx];
        }
        kbase[t] = kb; rbase[t] = rb; mflag[t] = mf;
    }
    __syncthreads();

    {
        uint32_t su  = (uint32_t)__cvta_generic_to_shared(sm_u);
        uint32_t sw  = (uint32_t)__cvta_generic_to_shared(sm_w);
        for (int c = t; c < 256; c += 128) {
            cp16(su + c * 16, gu + q * 1024 + c * 4);
            cp16(sw + c * 16, gw + q * 1024 + c * 4);
        }
        uint32_t smk = (uint32_t)__cvta_generic_to_shared(sm_k);
        uint32_t smr = (uint32_t)__cvta_generic_to_shared(sm_r);
        for (int c = t; c < S * 32; c += 128) {
            int s = c >> 5, j = c & 31;
            cp16(smk + s * 528 + j * 16, ksrc   + kbase[s] + j * 4);
            cp16(smr + s * 528 + j * 16, rpesrc + rbase[s] + j * 4);
        }
        asm volatile("cp.async.commit_group;");
        asm volatile("cp.async.wait_group 0;");
    }
    __syncthreads();

    // scores: thread = (s, i-half), 8 merged accumulators, float4 LDS.
    {
        int half = t >> 6, s = t & 63;
        if (s < S) {
            const float* kk = &sm_k[s * 132 + half * 64];
            const float* rr = &sm_r[s * 132 + half * 64];
            float acc[NH];
            #pragma unroll
            for (int n = 0; n < NH; ++n) acc[n] = 0.f;
            #pragma unroll 4
            for (int i = 0; i < 64; i += 4) {
                float4 k4 = *(const float4*)(kk + i);
                float4 r4 = *(const float4*)(rr + i);
                #pragma unroll
                for (int n = 0; n < NH; ++n) {
                    float4 u4 = *(const float4*)(sm_u + n * H + half * 64 + i);
                    float4 w4 = *(const float4*)(sm_w + n * H + half * 64 + i);
                    acc[n] += k4.x * u4.x + k4.y * u4.y + k4.z * u4.z + k4.w * u4.w
                            + r4.x * w4.x + r4.y * w4.y + r4.z * w4.z + r4.w * w4.w;
                }
            }
            float* dst = half ? sm_sc1 : sm_sc;
            #pragma unroll
            for (int n = 0; n < NH; ++n) dst[s * NH + n] = acc[n];
        }
    }
    __syncthreads();

    // softmax per head (merge halves, mask, 8 lanes per head).
    if (t < 64) {
        int n = t >> 3, j = t & 7;
        float mx = -1e30f;
        for (int s = j; s < S; s += 8) {
            float v = (sm_sc[s * NH + n] + sm_sc1[s * NH + n]) * 0.25f;
            if (mflag[s]) v = -1e9f;
            sm_sc[s * NH + n] = v;
            mx = fmaxf(mx, v);
        }
        #pragma unroll
        for (int o = 4; o; o >>= 1) mx = fmaxf(mx, __shfl_xor_sync(0xffffffffu, mx, o));
        float sum = 0.f;
        for (int s = j; s < S; s += 8) {
            float p = __expf(sm_sc[s * NH + n] - mx);
            sm_sc[s * NH + n] = p; sum += p;
        }
        #pragma unroll
        for (int o = 4; o; o >>= 1) sum += __shfl_xor_sync(0xffffffffu, sum, o);
        float inv = 1.f / sum;
        for (int s = j; s < S; s += 8) sm_sc[s * NH + n] *= inv;
    }
    __syncthreads();

    // vbar[n][t] = sum_s p[n,s] k[s,t]; rbar likewise.
    {
        float vb[NH], rb2[NH];
        #pragma unroll
        for (int n = 0; n < NH; ++n) { vb[n] = 0.f; rb2[n] = 0.f; }
        for (int s = 0; s < S; ++s) {
            float kv = sm_k[s * 132 + t];
            float rv = sm_r[s * 132 + t];
            float4 p0 = *(const float4*)&sm_sc[s * NH];
            float4 p1 = *(const float4*)&sm_sc[s * NH + 4];
            vb[0] += p0.x * kv;  rb2[0] += p0.x * rv;
            vb[1] += p0.y * kv;  rb2[1] += p0.y * rv;
            vb[2] += p0.z * kv;  rb2[2] += p0.z * rv;
            vb[3] += p0.w * kv;  rb2[3] += p0.w * rv;
            vb[4] += p1.x * kv;  rb2[4] += p1.x * rv;
            vb[5] += p1.y * kv;  rb2[5] += p1.y * rv;
            vb[6] += p1.z * kv;  rb2[6] += p1.z * rv;
            vb[7] += p1.w * kv;  rb2[7] += p1.w * rv;
        }
        #pragma unroll
        for (int n = 0; n < NH; ++n) {
            gvb[q * 1024 + n * H + t] = vb[n];
            grb[q * 1024 + n * H + t] = rb2[n];
        }
    }
}

// ---------------- Kernel C: of = vb@Wv + rb@Wrv (per head); x += of@Wo -------
// block = 8 queries, 256 threads; i-reduction split across groups.
__global__ __launch_bounds__(256) void out_proj(
    const float* __restrict__ xin,
    const float* __restrict__ gvb, const float* __restrict__ grb,
    const float* __restrict__ Wv, const float* __restrict__ Wrv,
    const float* __restrict__ Wo,
    float* __restrict__ xout)
{
    __shared__ float sof[8][128];
    __shared__ float part[2][8][128];

    const int tid = threadIdx.x;
    const int t = tid & 127, g = tid >> 7;
    const int q0 = blockIdx.x * 8;
    const int n = t >> 4;
    const int i0 = g * 64;

    // of partials: group g reduces i in [i0, i0+64)
    {
        float acc[8];
        #pragma unroll
        for (int q = 0; q < 8; ++q) acc[q] = 0.f;
        #pragma unroll 4
        for (int ii = 0; ii < 64; ++ii) {
            int i = i0 + ii;
            float wv = Wv [i * H + t];
            float wr = Wrv[i * H + t];
            #pragma unroll
            for (int q = 0; q < 8; ++q)
                acc[q] += gvb[(q0 + q) * 1024 + n * H + i] * wv
                        + grb[(q0 + q) * 1024 + n * H + i] * wr;
        }
        #pragma unroll
        for (int q = 0; q < 8; ++q) part[g][q][t] = acc[q];
    }
    __syncthreads();
    if (g == 0) {
        #pragma unroll
        for (int q = 0; q < 8; ++q) sof[q][t] = part[0][q][t] + part[1][q][t];
    }
    __syncthreads();

    // Wo partials: group g reduces i in [i0, i0+64)
    {
        float o[8];
        #pragma unroll
        for (int q = 0; q < 8; ++q) o[q] = 0.f;
        #pragma unroll 4
        for (int ii = 0; ii < 64; ++ii) {
            int i = i0 + ii;
            float wo = Wo[i * H + t];
            #pragma unroll
            for (int q = 0; q < 8; ++q) o[q] += sof[q][i] * wo;
        }
        #pragma unroll
        for (int q = 0; q < 8; ++q) part[g][q][t] = o[q];
    }
    __syncthreads();
    if (g == 0) {
        #pragma unroll
        for (int q = 0; q < 8; ++q)
            xout[(q0 + q) * H + t] =
                xin[(q0 + q) * H + t] + part[0][q][t] + part[1][q][t];
    }
}

extern "C" void kernel_launch(void* const* d_in, const int* in_sizes, int n_in,
                              void* d_out, int out_size)
{
    bool sig = (in_sizes[6] == 32768);

    const float* x_m    = (const float*)d_in[0];
    const float* x_a    = (const float*)d_in[1];
    const float* x_pl   = (const float*)d_in[2];
    const float* rpe_t  = (const float*)d_in[3];
    const float* rpe_pl = (const float*)d_in[4];
    const float* rpe_a  = (const float*)d_in[5];

    const float* W[3][6];
    int wb = sig ? 6 : 11;
    for (int s = 0; s < 3; ++s)
        for (int j = 0; j < 6; ++j)
            W[s][j] = (const float*)d_in[wb + s * 6 + j];

    int kb = sig ? 24 : 6;
    const int* knn_pl = (const int*)d_in[kb + 0];
    const int* knn_a  = (const int*)d_in[kb + 1];
    const unsigned char* mk_t  = (const unsigned char*)d_in[kb + 2];
    const unsigned char* mk_pl = (const unsigned char*)d_in[kb + 3];
    const unsigned char* mk_a  = (const unsigned char*)d_in[kb + 4];

    cudaFuncSetAttribute(attn_core, cudaFuncAttributeMaxDynamicSharedMemorySize, 65088);

    float *buf0, *buf1, *wt, *gu, *gw, *gvb, *grb;
    cudaGetSymbolAddress((void**)&buf0, g_buf0);
    cudaGetSymbolAddress((void**)&buf1, g_buf1);
    cudaGetSymbolAddress((void**)&wt,   g_WT);
    cudaGetSymbolAddress((void**)&gu,   g_u);
    cudaGetSymbolAddress((void**)&gw,   g_w);
    cudaGetSymbolAddress((void**)&gvb,  g_vb);
    cudaGetSymbolAddress((void**)&grb,  g_rb);

    transpose_k<<<48, 128>>>(W[0][1], W[0][3], W[1][1], W[1][3], W[2][1], W[2][3]);

    const int Ss[3] = {50, 32, 16};
    const float* cur = x_m;
    float* bufs[2] = {buf0, buf1};
    int bi = 0;

    for (int l = 0; l < 2; ++l) {
        for (int s = 0; s < 3; ++s) {
            float* outp = (l == 1 && s == 2) ? (float*)d_out : bufs[bi];
            int S = Ss[s];
            const float* ksrc = (s == 1) ? x_pl : x_a;
            const float* rp   = (s == 0) ? rpe_t : (s == 1) ? rpe_pl : rpe_a;
            const int*   kn   = (s == 1) ? knn_pl : (s == 2) ? knn_a : (const int*)0;
            const unsigned char* mk = (s == 0) ? mk_t : (s == 1) ? mk_pl : mk_a;

            const float* Wq   = W[s][0] + l * H * H;
            const float* Wv   = W[s][2] + l * H * H;
            const float* Wrv  = W[s][4] + l * H * H;
            const float* Wo   = W[s][5] + l * H * H;
            const float* WkT  = wt + ((s * 2 + 0) * 2 + l) * H * H;
            const float* WrkT = wt + ((s * 2 + 1) * 2 + l) * H * H;

            stage_uw<<<NQ / 8, 256>>>(cur, Wq, WkT, WrkT, gu, gw);

            size_t smemB = (size_t)(3072 + S * 264) * sizeof(float);
            attn_core<<<NQ, 128, smemB>>>(gu, gw, ksrc, rp, kn, mk,
                                          gvb, grb, s + 1, S);

            out_proj<<<NQ / 8, 256>>>(cur, gvb, grb, Wv, Wrv, Wo, outp);

            cur = outp;
            bi ^= 1;
        }
    }
}

// round 7
// speedup vs baseline: 1.5039x; 1.2665x over previous
#include <cuda_runtime.h>
#include <cstdint>

#define H  128
#define NH 8
#define NQ 2304

__device__ float g_WT[12 * H * H];
__device__ float g_u [NQ * 1024];
__device__ float g_w [NQ * 1024];
__device__ float g_vb[NQ * 1024];
__device__ float g_rb[NQ * 1024];
__device__ float g_buf0[NQ * H];
__device__ float g_buf1[NQ * H];

__global__ void transpose_k(const float* p0, const float* p1, const float* p2,
                            const float* p3, const float* p4, const float* p5)
{
    const float* ps[6] = {p0, p1, p2, p3, p4, p5};
    int slot = blockIdx.x >> 2;                  // 0..11
    int part = blockIdx.x & 3;
    const float* Wm = ps[slot >> 1] + (slot & 1) * H * H;
    float* O = g_WT + slot * H * H;
    int t = threadIdx.x;
    for (int c = part * 32; c < part * 32 + 32; ++c)
        O[c * H + t] = Wm[t * H + c];
}

__device__ __forceinline__ void cp16(uint32_t dst, const float* src) {
    asm volatile("cp.async.cg.shared.global [%0], [%1], 16;" :: "r"(dst), "l"(src));
}

// ---- helper: u/w head projection from qh in smem -----------------------------
__device__ __forceinline__ void uw_heads(
    const float (*sqh)[128], int g, int t, int q0,
    const float* __restrict__ WkT, const float* __restrict__ WrkT,
    float* __restrict__ gu, float* __restrict__ gw)
{
    #pragma unroll 1
    for (int nn = 0; nn < 4; ++nn) {
        int n = 4 * g + nn;
        float wk[16], wr[16];
        #pragma unroll
        for (int d = 0; d < 16; ++d) {
            wk[d] = WkT [(n * 16 + d) * H + t];
            wr[d] = WrkT[(n * 16 + d) * H + t];
        }
        float uo[4], wo4[4];
        #pragma unroll
        for (int q = 0; q < 4; ++q) { uo[q] = 0.f; wo4[q] = 0.f; }
        #pragma unroll
        for (int d = 0; d < 16; ++d) {
            #pragma unroll
            for (int q = 0; q < 4; ++q) {
                float qv = sqh[q][n * 16 + d];
                uo[q]  += qv * wk[d];
                wo4[q] += qv * wr[d];
            }
        }
        #pragma unroll
        for (int q = 0; q < 4; ++q) {
            gu[(q0 + q) * 1024 + n * H + t] = uo[q];
            gw[(q0 + q) * 1024 + n * H + t] = wo4[q];
        }
    }
}

// ---------------- Kernel A (first stage only): qh = x@Wq; u/w ----------------
// block = 4 queries, 256 threads.
__global__ __launch_bounds__(256) void stage_uw(
    const float* __restrict__ xin,
    const float* __restrict__ Wq,
    const float* __restrict__ WkT, const float* __restrict__ WrkT,
    float* __restrict__ gu, float* __restrict__ gw)
{
    __shared__ float sx [4][128];
    __shared__ float sqh[4][128];
    const int tid = threadIdx.x;
    const int t = tid & 127, g = tid >> 7;
    const int q0 = blockIdx.x * 4;

    for (int e = tid; e < 512; e += 256)
        sx[e >> 7][e & 127] = xin[q0 * H + e];
    __syncthreads();

    {
        float a0 = 0.f, a1 = 0.f;
        const float* x0 = sx[2 * g];
        const float* x1 = sx[2 * g + 1];
        #pragma unroll 8
        for (int i = 0; i < H; ++i) {
            float wv = Wq[i * H + t];
            a0 += x0[i] * wv; a1 += x1[i] * wv;
        }
        sqh[2 * g    ][t] = a0;
        sqh[2 * g + 1][t] = a1;
    }
    __syncthreads();
    uw_heads(sqh, g, t, q0, WkT, WrkT, gu, gw);
}

// ---------------- Kernel B: weight-free attention core -----------------------
__global__ __launch_bounds__(128) void attn_core(
    const float* __restrict__ gu, const float* __restrict__ gw,
    const float* __restrict__ ksrc, const float* __restrict__ rpesrc,
    const int* __restrict__ knn, const unsigned char* __restrict__ mask,
    float* __restrict__ gvb, float* __restrict__ grb,
    int stage, int S)
{
    extern __shared__ float sm[];
    float* sm_u   = sm;              // 1024
    float* sm_w   = sm + 1024;       // 1024
    float* sm_sc  = sm + 2048;       // 512
    float* sm_sc1 = sm + 2560;       // 512
    float* sm_k   = sm + 3072;       // S*132
    float* sm_r   = sm_k + S * 132;  // S*132

    __shared__ int kbase[64], rbase[64], mflag[64];

    const int q = blockIdx.x;
    const int t = threadIdx.x;

    if (t < S) {
        int kb, rb, mf;
        if (stage == 1) {
            kb = (q * S + t) * H; rb = kb;
            mf = mask[q * S + t];
        } else if (stage == 2) {
            int idx = knn[q * 32 + t];
            kb = (q * 128 + idx) * H; rb = kb;
            mf = mask[q * 128 + idx];
        } else {
            int g = q / 48, qn = q % 48;
            int idx = knn[(g * 48 + qn) * 16 + t];
            kb = ((g * 48 + idx) * 50 + 49) * H;
            rb = ((g * 48 + qn) * 48 + idx) * H;
            mf = mask[(g * 48 + qn) * 48 + idx];
        }
        kbase[t] = kb; rbase[t] = rb; mflag[t] = mf;
    }
    __syncthreads();

    {
        uint32_t su  = (uint32_t)__cvta_generic_to_shared(sm_u);
        uint32_t sw  = (uint32_t)__cvta_generic_to_shared(sm_w);
        for (int c = t; c < 256; c += 128) {
            cp16(su + c * 16, gu + q * 1024 + c * 4);
            cp16(sw + c * 16, gw + q * 1024 + c * 4);
        }
        uint32_t smk = (uint32_t)__cvta_generic_to_shared(sm_k);
        uint32_t smr = (uint32_t)__cvta_generic_to_shared(sm_r);
        for (int c = t; c < S * 32; c += 128) {
            int s = c >> 5, j = c & 31;
            cp16(smk + s * 528 + j * 16, ksrc   + kbase[s] + j * 4);
            cp16(smr + s * 528 + j * 16, rpesrc + rbase[s] + j * 4);
        }
        asm volatile("cp.async.commit_group;");
        asm volatile("cp.async.wait_group 0;");
    }
    __syncthreads();

    {
        int half = t >> 6, s = t & 63;
        if (s < S) {
            const float* kk = &sm_k[s * 132 + half * 64];
            const float* rr = &sm_r[s * 132 + half * 64];
            float acc[NH];
            #pragma unroll
            for (int n = 0; n < NH; ++n) acc[n] = 0.f;
            #pragma unroll 4
            for (int i = 0; i < 64; i += 4) {
                float4 k4 = *(const float4*)(kk + i);
                float4 r4 = *(const float4*)(rr + i);
                #pragma unroll
                for (int n = 0; n < NH; ++n) {
                    float4 u4 = *(const float4*)(sm_u + n * H + half * 64 + i);
                    float4 w4 = *(const float4*)(sm_w + n * H + half * 64 + i);
                    acc[n] += k4.x * u4.x + k4.y * u4.y + k4.z * u4.z + k4.w * u4.w
                            + r4.x * w4.x + r4.y * w4.y + r4.z * w4.z + r4.w * w4.w;
                }
            }
            float* dst = half ? sm_sc1 : sm_sc;
            #pragma unroll
            for (int n = 0; n < NH; ++n) dst[s * NH + n] = acc[n];
        }
    }
    __syncthreads();

    if (t < 64) {
        int n = t >> 3, j = t & 7;
        float mx = -1e30f;
        for (int s = j; s < S; s += 8) {
            float v = (sm_sc[s * NH + n] + sm_sc1[s * NH + n]) * 0.25f;
            if (mflag[s]) v = -1e9f;
            sm_sc[s * NH + n] = v;
            mx = fmaxf(mx, v);
        }
        #pragma unroll
        for (int o = 4; o; o >>= 1) mx = fmaxf(mx, __shfl_xor_sync(0xffffffffu, mx, o));
        float sum = 0.f;
        for (int s = j; s < S; s += 8) {
            float p = __expf(sm_sc[s * NH + n] - mx);
            sm_sc[s * NH + n] = p; sum += p;
        }
        #pragma unroll
        for (int o = 4; o; o >>= 1) sum += __shfl_xor_sync(0xffffffffu, sum, o);
        float inv = 1.f / sum;
        for (int s = j; s < S; s += 8) sm_sc[s * NH + n] *= inv;
    }
    __syncthreads();

    {
        float vb[NH], rb2[NH];
        #pragma unroll
        for (int n = 0; n < NH; ++n) { vb[n] = 0.f; rb2[n] = 0.f; }
        for (int s = 0; s < S; ++s) {
            float kv = sm_k[s * 132 + t];
            float rv = sm_r[s * 132 + t];
            float4 p0 = *(const float4*)&sm_sc[s * NH];
            float4 p1 = *(const float4*)&sm_sc[s * NH + 4];
            vb[0] += p0.x * kv;  rb2[0] += p0.x * rv;
            vb[1] += p0.y * kv;  rb2[1] += p0.y * rv;
            vb[2] += p0.z * kv;  rb2[2] += p0.z * rv;
            vb[3] += p0.w * kv;  rb2[3] += p0.w * rv;
            vb[4] += p1.x * kv;  rb2[4] += p1.x * rv;
            vb[5] += p1.y * kv;  rb2[5] += p1.y * rv;
            vb[6] += p1.z * kv;  rb2[6] += p1.z * rv;
            vb[7] += p1.w * kv;  rb2[7] += p1.w * rv;
        }
        #pragma unroll
        for (int n = 0; n < NH; ++n) {
            gvb[q * 1024 + n * H + t] = vb[n];
            grb[q * 1024 + n * H + t] = rb2[n];
        }
    }
}

// ---------------- Kernel C+A': out_proj fused with next-stage uw -------------
// block = 4 queries, 256 threads, grid 576.
__global__ __launch_bounds__(256) void out_proj_uw(
    const float* __restrict__ xin,
    const float* __restrict__ gvb, const float* __restrict__ grb,
    const float* __restrict__ Wv, const float* __restrict__ Wrv,
    const float* __restrict__ Wo,
    float* __restrict__ xout,
    const float* __restrict__ Wq2,
    const float* __restrict__ WkT2, const float* __restrict__ WrkT2,
    float* __restrict__ gu, float* __restrict__ gw, int do_next)
{
    __shared__ float svb[4][1024];
    __shared__ float srb[4][1024];
    __shared__ float sof[4][128];
    __shared__ float sxo[4][128];
    __shared__ float part[2][4][128];

    const int tid = threadIdx.x;
    const int t = tid & 127, g = tid >> 7;
    const int q0 = blockIdx.x * 4;
    const int n = t >> 4;
    const int i0 = g * 64;

    // Stage vb/rb into smem (bulk cp.async, one wait).
    {
        uint32_t a = (uint32_t)__cvta_generic_to_shared(&svb[0][0]);
        uint32_t b = (uint32_t)__cvta_generic_to_shared(&srb[0][0]);
        for (int c = tid; c < 1024; c += 256) {
            cp16(a + c * 16, gvb + q0 * 1024 + c * 4);
            cp16(b + c * 16, grb + q0 * 1024 + c * 4);
        }
        asm volatile("cp.async.commit_group;");
        asm volatile("cp.async.wait_group 0;");
    }
    __syncthreads();

    // Phase 1: of[q][t] = vb[q][n]·Wv[:,t] + rb[q][n]·Wrv[:,t]  (i split by group)
    {
        float a0 = 0.f, a1 = 0.f, a2 = 0.f, a3 = 0.f;
        #pragma unroll 4
        for (int ii = 0; ii < 64; ii += 2) {
            int i = i0 + ii;
            float wv0 = Wv [i * H + t],      wr0 = Wrv[i * H + t];
            float wv1 = Wv [(i + 1) * H + t], wr1 = Wrv[(i + 1) * H + t];
            a0 += svb[0][n * 128 + i] * wv0 + srb[0][n * 128 + i] * wr0
                + svb[0][n * 128 + i + 1] * wv1 + srb[0][n * 128 + i + 1] * wr1;
            a1 += svb[1][n * 128 + i] * wv0 + srb[1][n * 128 + i] * wr0
                + svb[1][n * 128 + i + 1] * wv1 + srb[1][n * 128 + i + 1] * wr1;
            a2 += svb[2][n * 128 + i] * wv0 + srb[2][n * 128 + i] * wr0
                + svb[2][n * 128 + i + 1] * wv1 + srb[2][n * 128 + i + 1] * wr1;
            a3 += svb[3][n * 128 + i] * wv0 + srb[3][n * 128 + i] * wr0
                + svb[3][n * 128 + i + 1] * wv1 + srb[3][n * 128 + i + 1] * wr1;
        }
        part[g][0][t] = a0; part[g][1][t] = a1;
        part[g][2][t] = a2; part[g][3][t] = a3;
    }
    __syncthreads();
    if (g == 0) {
        #pragma unroll
        for (int q = 0; q < 4; ++q) sof[q][t] = part[0][q][t] + part[1][q][t];
    }
    __syncthreads();

    // Phase 2: x_out = x + of @ Wo  (i split by group)
    {
        float o0 = 0.f, o1 = 0.f, o2 = 0.f, o3 = 0.f;
        #pragma unroll 4
        for (int ii = 0; ii < 64; ++ii) {
            int i = i0 + ii;
            float wo = Wo[i * H + t];
            o0 += sof[0][i] * wo; o1 += sof[1][i] * wo;
            o2 += sof[2][i] * wo; o3 += sof[3][i] * wo;
        }
        part[g][0][t] = o0; part[g][1][t] = o1;
        part[g][2][t] = o2; part[g][3][t] = o3;
    }
    __syncthreads();
    if (g == 0) {
        #pragma unroll
        for (int q = 0; q < 4; ++q) {
            float v = xin[(q0 + q) * H + t] + part[0][q][t] + part[1][q][t];
            sxo[q][t] = v;
            xout[(q0 + q) * H + t] = v;
        }
    }
    __syncthreads();

    if (!do_next) return;

    // Phase 3: next-stage qh = x_out @ Wq2  (group g does queries 2g, 2g+1)
    {
        float a0 = 0.f, a1 = 0.f;
        const float* x0 = sxo[2 * g];
        const float* x1 = sxo[2 * g + 1];
        #pragma unroll 8
        for (int i = 0; i < H; ++i) {
            float wv = Wq2[i * H + t];
            a0 += x0[i] * wv; a1 += x1[i] * wv;
        }
        part[0][2 * g    ][t] = a0;
        part[0][2 * g + 1][t] = a1;
    }
    __syncthreads();

    // Phase 4: next-stage u/w (reuse part[0] as qh buffer).
    uw_heads((const float (*)[128])part[0], g, t, q0, WkT2, WrkT2, gu, gw);
}

extern "C" void kernel_launch(void* const* d_in, const int* in_sizes, int n_in,
                              void* d_out, int out_size)
{
    bool sig = (in_sizes[6] == 32768);

    const float* x_m    = (const float*)d_in[0];
    const float* x_a    = (const float*)d_in[1];
    const float* x_pl   = (const float*)d_in[2];
    const float* rpe_t  = (const float*)d_in[3];
    const float* rpe_pl = (const float*)d_in[4];
    const float* rpe_a  = (const float*)d_in[5];

    const float* W[3][6];
    int wb = sig ? 6 : 11;
    for (int s = 0; s < 3; ++s)
        for (int j = 0; j < 6; ++j)
            W[s][j] = (const float*)d_in[wb + s * 6 + j];

    int kb = sig ? 24 : 6;
    const int* knn_pl = (const int*)d_in[kb + 0];
    const int* knn_a  = (const int*)d_in[kb + 1];
    const unsigned char* mk_t  = (const unsigned char*)d_in[kb + 2];
    const unsigned char* mk_pl = (const unsigned char*)d_in[kb + 3];
    const unsigned char* mk_a  = (const unsigned char*)d_in[kb + 4];

    cudaFuncSetAttribute(attn_core, cudaFuncAttributeMaxDynamicSharedMemorySize, 65088);

    float *buf0, *buf1, *wt, *gu, *gw, *gvb, *grb;
    cudaGetSymbolAddress((void**)&buf0, g_buf0);
    cudaGetSymbolAddress((void**)&buf1, g_buf1);
    cudaGetSymbolAddress((void**)&wt,   g_WT);
    cudaGetSymbolAddress((void**)&gu,   g_u);
    cudaGetSymbolAddress((void**)&gw,   g_w);
    cudaGetSymbolAddress((void**)&gvb,  g_vb);
    cudaGetSymbolAddress((void**)&grb,  g_rb);

    transpose_k<<<48, 128>>>(W[0][1], W[0][3], W[1][1], W[1][3], W[2][1], W[2][3]);

    const int Ss[3] = {50, 32, 16};
    const float* cur = x_m;
    float* bufs[2] = {buf0, buf1};
    int bi = 0;

    // First-stage u/w.
    stage_uw<<<NQ / 4, 256>>>(x_m, W[0][0],
                              wt + ((0 * 2 + 0) * 2 + 0) * H * H,
                              wt + ((0 * 2 + 1) * 2 + 0) * H * H, gu, gw);

    for (int idx = 0; idx < 6; ++idx) {
        int l = idx / 3, s = idx % 3;
        int l2 = (idx + 1) / 3, s2 = (idx + 1) % 3;     // next stage (if any)
        float* outp = (idx == 5) ? (float*)d_out : bufs[bi];
        int S = Ss[s];
        const float* ksrc = (s == 1) ? x_pl : x_a;
        const float* rp   = (s == 0) ? rpe_t : (s == 1) ? rpe_pl : rpe_a;
        const int*   kn   = (s == 1) ? knn_pl : (s == 2) ? knn_a : (const int*)0;
        const unsigned char* mk = (s == 0) ? mk_t : (s == 1) ? mk_pl : mk_a;

        const float* Wv  = W[s][2] + l * H * H;
        const float* Wrv = W[s][4] + l * H * H;
        const float* Wo  = W[s][5] + l * H * H;

        size_t smemB = (size_t)(3072 + S * 264) * sizeof(float);
        attn_core<<<NQ, 128, smemB>>>(gu, gw, ksrc, rp, kn, mk,
                                      gvb, grb, s + 1, S);

        int do_next = (idx < 5);
        const float* Wq2   = do_next ? W[s2][0] + l2 * H * H : Wv;
        const float* WkT2  = do_next ? wt + ((s2 * 2 + 0) * 2 + l2) * H * H : Wv;
        const float* WrkT2 = do_next ? wt + ((s2 * 2 + 1) * 2 + l2) * H * H : Wv;

        out_proj_uw<<<NQ / 4, 256>>>(cur, gvb, grb, Wv, Wrv, Wo, outp,
                                     Wq2, WkT2, WrkT2, gu, gw, do_next);
        cur = outp;
        bi ^= 1;
    }
}